// round 3
// baseline (speedup 1.0000x reference)
#include <cuda_runtime.h>

#define Hd 64
#define Vd 64
#define INNER 24
#define SEQ 32
#define CAP 8
#define NPAIR 15
#define LRc 0.05f
#define B1c 0.9f
#define B2c 0.999f
#define EPSc 1e-8f

#define NW1 (Hd*INNER)            // 1536
#define OFF_B1 NW1                // 1536
#define OFF_W2 (NW1 + INNER)      // 1560
#define OFF_B2 (OFF_W2 + INNER*Hd)// 3096
#define NPARAM (OFF_B2 + Hd)      // 3160

struct SmemLayout {
    float h[SEQ*Hd];     // 2048 — embeddings, then LN'd encodings
    float P[NPARAM];     // MLP params (w1 | b1 | w2 | b2)
    float M[NPARAM];     // Adam m   (aliased as encode scratch before Adam init)
    float Vv[NPARAM];    // Adam v   (aliased as encode scratch before Adam init)
    float z1[INNER];
    float a1[INNER];
    float dz1[INNER];
    float dout[Hd];
    float scores[NPAIR + 1];
    float esc[CAP];
    int   ord[CAP];
    int   toks[SEQ];
};

__device__ __forceinline__ float wredsum(float x) {
    #pragma unroll
    for (int o = 16; o; o >>= 1) x += __shfl_xor_sync(0xffffffffu, x, o);
    return x;
}

__device__ __forceinline__ void adam_upd(float* __restrict__ P, float* __restrict__ M,
                                         float* __restrict__ Vv, int q, float g,
                                         float inv1, float inv2) {
    float m = fmaf(B1c, M[q], (1.0f - B1c) * g);
    float v = fmaf(B2c, Vv[q], (1.0f - B2c) * g * g);
    M[q] = m; Vv[q] = v;
    float mh = m * inv1;
    float vh = v * inv2;
    float r  = __frsqrt_rn(vh);            // 1/sqrt(vh), inf at 0
    float sq = (vh > 0.0f) ? vh * r : 0.0f; // sqrt(vh), 0-safe
    float upd = __fdividef(mh, sq + EPSc);
    P[q] = fmaf(-LRc, upd, P[q]);
}

__global__ void __launch_bounds__(128, 4) ttt_kernel(
    const int*   __restrict__ seqs,
    const float* __restrict__ embed,
    const float* __restrict__ ffw1, const float* __restrict__ ffb1,
    const float* __restrict__ ffw2, const float* __restrict__ ffb2,
    const float* __restrict__ lng,  const float* __restrict__ lnb,
    const float* __restrict__ scw,  const float* __restrict__ scb,
    const float* __restrict__ mw1,  const float* __restrict__ mb1,
    const float* __restrict__ mw2,  const float* __restrict__ mb2,
    const float* __restrict__ outw, const float* __restrict__ outb,
    float* __restrict__ out)
{
    __shared__ SmemLayout s;
    const int tid  = threadIdx.x;
    const int lane = tid & 31;
    const int w    = tid >> 5;       // 4 warps
    const int b    = blockIdx.x;

    // ---- load tokens + embeddings into h ----
    if (tid < SEQ) s.toks[tid] = seqs[b * SEQ + tid];
    __syncthreads();
    for (int idx = tid; idx < SEQ * Hd; idx += 128) {
        int t = idx >> 6, i = idx & 63;
        s.h[idx] = embed[s.toks[t] * Hd + i];
    }
    __syncthreads();

    float* scratch = s.M;  // encode scratch: 4 warps * 1024 floats (fits in M+Vv)

    // ---- encode: warp w handles tokens {w, w+4, ..., w+28} ----
    {
        // layer 1: hidden[8 tokens][4 cols per lane]
        float bb0 = ffb1[lane], bb1 = ffb1[lane + 32], bb2 = ffb1[lane + 64], bb3 = ffb1[lane + 96];
        float acc[8][4];
        #pragma unroll
        for (int tk = 0; tk < 8; tk++) { acc[tk][0]=bb0; acc[tk][1]=bb1; acc[tk][2]=bb2; acc[tk][3]=bb3; }
        #pragma unroll 4
        for (int i = 0; i < Hd; i++) {
            float w0 = ffw1[i*128 + lane];
            float w1_ = ffw1[i*128 + lane + 32];
            float w2_ = ffw1[i*128 + lane + 64];
            float w3_ = ffw1[i*128 + lane + 96];
            #pragma unroll
            for (int tk = 0; tk < 8; tk++) {
                float ev = s.h[(w + 4*tk)*Hd + i];
                acc[tk][0] = fmaf(ev, w0,  acc[tk][0]);
                acc[tk][1] = fmaf(ev, w1_, acc[tk][1]);
                acc[tk][2] = fmaf(ev, w2_, acc[tk][2]);
                acc[tk][3] = fmaf(ev, w3_, acc[tk][3]);
            }
        }
        #pragma unroll
        for (int tk = 0; tk < 8; tk++)
            #pragma unroll
            for (int c = 0; c < 4; c++)
                scratch[w*1024 + tk*128 + lane + 32*c] = fmaxf(acc[tk][c], 0.0f);
        __syncwarp();

        // layer 2: f[8 tokens][2 cols per lane]
        float fb0 = ffb2[lane], fb1 = ffb2[lane + 32];
        float a2[8][2];
        #pragma unroll
        for (int tk = 0; tk < 8; tk++) { a2[tk][0] = fb0; a2[tk][1] = fb1; }
        #pragma unroll 4
        for (int i = 0; i < 2*Hd; i++) {
            float w0 = ffw2[i*64 + lane];
            float w1_ = ffw2[i*64 + lane + 32];
            #pragma unroll
            for (int tk = 0; tk < 8; tk++) {
                float hv = scratch[w*1024 + tk*128 + i];
                a2[tk][0] = fmaf(hv, w0,  a2[tk][0]);
                a2[tk][1] = fmaf(hv, w1_, a2[tk][1]);
            }
        }

        // residual + layernorm per token
        float g0 = lng[lane], g1 = lng[lane + 32];
        float be0 = lnb[lane], be1 = lnb[lane + 32];
        #pragma unroll
        for (int tk = 0; tk < 8; tk++) {
            int t = w + 4*tk;
            float x0 = s.h[t*Hd + lane]      + a2[tk][0];
            float x1 = s.h[t*Hd + lane + 32] + a2[tk][1];
            float mean = wredsum(x0 + x1) * (1.0f/64.0f);
            float d0 = x0 - mean, d1 = x1 - mean;
            float var = wredsum(d0*d0 + d1*d1) * (1.0f/64.0f);
            float rs = rsqrtf(var + 1e-5f);
            s.h[t*Hd + lane]      = fmaf(d0*rs, g0, be0);
            s.h[t*Hd + lane + 32] = fmaf(d1*rs, g1, be1);
        }
    }
    __syncthreads();

    // ---- scores for the 15 (k,v) pairs ----
    for (int p = w; p < NPAIR; p += 4) {
        const float* kk = &s.h[(2*p)     * Hd];
        const float* vv = &s.h[(2*p + 1) * Hd];
        float acc = kk[lane]      * scw[lane]
                  + kk[lane + 32] * scw[lane + 32]
                  + vv[lane]      * scw[lane + 64]
                  + vv[lane + 32] * scw[lane + 96];
        acc = wredsum(acc);
        if (lane == 0) s.scores[p] = acc + scb[0];
    }
    __syncthreads();

    // ---- evict-min buffer (thread 0) + Adam state init (all threads) ----
    if (tid == 0) {
        #pragma unroll
        for (int i = 0; i < CAP; i++) { s.ord[i] = i; s.esc[i] = s.scores[i]; }
        for (int n = CAP; n < NPAIR; n++) {
            int mi = 0; float mv = s.esc[0];
            #pragma unroll
            for (int i = 1; i < CAP; i++) if (s.esc[i] < mv) { mv = s.esc[i]; mi = i; }
            for (int i = mi; i < CAP - 1; i++) { s.ord[i] = s.ord[i+1]; s.esc[i] = s.esc[i+1]; }
            s.ord[CAP-1] = n; s.esc[CAP-1] = s.scores[n];
        }
    }
    for (int q = tid; q < NPARAM; q += 128) {
        float pv;
        if (q < NW1)          pv = mw1[q];
        else if (q < OFF_W2)  pv = mb1[q - OFF_B1];
        else if (q < OFF_B2)  pv = mw2[q - OFF_W2];
        else                  pv = mb2[q - OFF_B2];
        s.P[q] = pv; s.M[q] = 0.0f; s.Vv[q] = 0.0f;
    }
    __syncthreads();

    // ---- 8 inner Adam steps ----
    float pb1 = 1.0f, pb2 = 1.0f;
    for (int st = 0; st < CAP; st++) {
        pb1 *= B1c; pb2 *= B2c;
        float inv1 = 1.0f / (1.0f - pb1);
        float inv2 = 1.0f / (1.0f - pb2);
        int koff = (2 * s.ord[st]) * Hd;
        int voff = koff + Hd;

        // forward layer 1
        if (tid < INNER) {
            int j = tid;
            float a0=0.f, a1_=0.f, a2_=0.f, a3=0.f;
            #pragma unroll
            for (int i = 0; i < Hd; i += 4) {
                a0  = fmaf(s.h[koff+i],   s.P[(i)  *INNER + j], a0);
                a1_ = fmaf(s.h[koff+i+1], s.P[(i+1)*INNER + j], a1_);
                a2_ = fmaf(s.h[koff+i+2], s.P[(i+2)*INNER + j], a2_);
                a3  = fmaf(s.h[koff+i+3], s.P[(i+3)*INNER + j], a3);
            }
            float z = (a0 + a1_) + (a2_ + a3) + s.P[OFF_B1 + j];
            s.z1[j] = z;
            s.a1[j] = fmaxf(z, 0.0f);
        }
        __syncthreads();

        // forward layer 2 + output grad
        if (tid < Hd) {
            int o = tid;
            float acc = s.P[OFF_B2 + o];
            #pragma unroll
            for (int j = 0; j < INNER; j++)
                acc = fmaf(s.a1[j], s.P[OFF_W2 + j*Hd + o], acc);
            s.dout[o] = (acc - s.h[voff + o]) * (2.0f / 64.0f);
        }
        __syncthreads();

        // backward into hidden (rotated access: conflict-free)
        if (tid < INNER) {
            int j = tid;
            float acc = 0.0f;
            #pragma unroll 8
            for (int ii = 0; ii < Hd; ii++) {
                int o = (ii + j) & (Hd - 1);
                acc = fmaf(s.P[OFF_W2 + j*Hd + o], s.dout[o], acc);
            }
            s.dz1[j] = (s.z1[j] > 0.0f) ? acc : 0.0f;
        }
        __syncthreads();

        // parameter updates
        for (int q = tid; q < NW1; q += 128) {
            int i = q / INNER;
            int j = q - i * INNER;
            adam_upd(s.P, s.M, s.Vv, q, s.h[koff + i] * s.dz1[j], inv1, inv2);
        }
        if (tid < INNER)
            adam_upd(s.P, s.M, s.Vv, OFF_B1 + tid, s.dz1[tid], inv1, inv2);
        for (int q = tid; q < INNER*Hd; q += 128) {
            int j = q >> 6;
            int o = q & 63;
            adam_upd(s.P, s.M, s.Vv, OFF_W2 + q, s.a1[j] * s.dout[o], inv1, inv2);
        }
        if (tid < Hd)
            adam_upd(s.P, s.M, s.Vv, OFF_B2 + tid, s.dout[tid], inv1, inv2);
        __syncthreads();
    }

    // ---- query: mlp_fwd(p, h[30]) @ out_w + out_b ----
    {
        int qoff = (SEQ - 2) * Hd;
        if (tid < INNER) {
            int j = tid;
            float a0=0.f, a1_=0.f, a2_=0.f, a3=0.f;
            #pragma unroll
            for (int i = 0; i < Hd; i += 4) {
                a0  = fmaf(s.h[qoff+i],   s.P[(i)  *INNER + j], a0);
                a1_ = fmaf(s.h[qoff+i+1], s.P[(i+1)*INNER + j], a1_);
                a2_ = fmaf(s.h[qoff+i+2], s.P[(i+2)*INNER + j], a2_);
                a3  = fmaf(s.h[qoff+i+3], s.P[(i+3)*INNER + j], a3);
            }
            float z = (a0 + a1_) + (a2_ + a3) + s.P[OFF_B1 + j];
            s.a1[j] = fmaxf(z, 0.0f);
        }
        __syncthreads();
        if (tid < Hd) {
            int o = tid;
            float acc = s.P[OFF_B2 + o];
            #pragma unroll
            for (int j = 0; j < INNER; j++)
                acc = fmaf(s.a1[j], s.P[OFF_W2 + j*Hd + o], acc);
            s.dout[o] = acc;  // reuse as MLP output
        }
        __syncthreads();
        if (tid < Vd) {
            float acc = outb[tid];
            #pragma unroll 8
            for (int o = 0; o < Hd; o++)
                acc = fmaf(s.dout[o], outw[o*Vd + tid], acc);
            out[b * Vd + tid] = acc;
        }
    }
}

extern "C" void kernel_launch(void* const* d_in, const int* in_sizes, int n_in,
                              void* d_out, int out_size) {
    const int*   seqs  = (const int*)  d_in[0];
    const float* embed = (const float*)d_in[1];
    const float* ffw1  = (const float*)d_in[2];
    const float* ffb1  = (const float*)d_in[3];
    const float* ffw2  = (const float*)d_in[4];
    const float* ffb2  = (const float*)d_in[5];
    const float* lng   = (const float*)d_in[6];
    const float* lnb   = (const float*)d_in[7];
    const float* scw   = (const float*)d_in[8];
    const float* scb   = (const float*)d_in[9];
    const float* mw1   = (const float*)d_in[10];
    const float* mb1   = (const float*)d_in[11];
    const float* mw2   = (const float*)d_in[12];
    const float* mb2   = (const float*)d_in[13];
    const float* outw  = (const float*)d_in[14];
    const float* outb  = (const float*)d_in[15];
    float* out = (float*)d_out;

    int B = in_sizes[0] / SEQ;
    ttt_kernel<<<B, 128>>>(seqs, embed, ffw1, ffb1, ffw2, ffb2, lng, lnb,
                           scw, scb, mw1, mb1, mw2, mb2, outw, outb, out);
}

// round 6
// speedup vs baseline: 2.1973x; 2.1973x over previous
#include <cuda_runtime.h>

#define Hd 64
#define Vd 64
#define INNER 24
#define SEQ 32
#define CAP 8
#define NPAIR 15
#define LRc 0.05f
#define B1c 0.9f
#define B2c 0.999f
#define EPSc 1e-8f

#define NW1 (Hd*INNER)             // 1536
#define OFF_B1 NW1                 // 1536
#define OFF_W2 (NW1 + INNER)       // 1560
#define OFF_B2 (OFF_W2 + INNER*Hd) // 3096
#define NPARAM (OFF_B2 + Hd)       // 3160

struct __align__(16) SmemLayout {
    float h[SEQ*Hd];     // 2048
    float P[NPARAM];     // params  w1[i*24+j] | b1 | w2[j*64+o] | b2
    float M[NPARAM];     // Adam m  (aliased as encode scratch)
    float Vv[NPARAM];    // Adam v  (aliased as encode scratch)
    float a1[INNER];
    float dz1[INNER];
    float dout[Hd];
    float scores[NPAIR + 1];
    float esc[CAP];
    int   ord[CAP];
    int   toks[SEQ];
};

__device__ __forceinline__ float wredsum(float x) {
    #pragma unroll
    for (int o = 16; o; o >>= 1) x += __shfl_xor_sync(0xffffffffu, x, o);
    return x;
}

// Exact eps-folded Adam on a float2 pair:
//   mhat/(sqrt(vhat)+eps) == m/(sqrt(v)+eps*s2) * (inv1*s2),  s2 = sqrt(1-b2^t)
// so p += negC * m / (sqrt(v) + epsT), negC = -LR*inv1*s2, epsT = eps*s2.
__device__ __forceinline__ void adam2(float2* __restrict__ P2, float2* __restrict__ M2,
                                      float2* __restrict__ V2, int f,
                                      float gx, float gy, float negC, float epsT) {
    float2 m = M2[f], v = V2[f], p = P2[f];
    m.x = fmaf(B1c, m.x, 0.1f * gx);
    m.y = fmaf(B1c, m.y, 0.1f * gy);
    v.x = fmaf(B2c, v.x, 0.001f * gx * gx);
    v.y = fmaf(B2c, v.y, 0.001f * gy * gy);
    M2[f] = m; V2[f] = v;
    float rx = __frsqrt_rn(v.x);
    float ry = __frsqrt_rn(v.y);
    float sx = (v.x > 0.0f) ? v.x * rx : 0.0f;   // sqrt(v), 0-safe
    float sy = (v.y > 0.0f) ? v.y * ry : 0.0f;
    p.x = fmaf(negC, __fdividef(m.x, sx + epsT), p.x);
    p.y = fmaf(negC, __fdividef(m.y, sy + epsT), p.y);
    P2[f] = p;
}

__global__ void __launch_bounds__(128, 4) ttt_kernel(
    const int*   __restrict__ seqs,
    const float* __restrict__ embed,
    const float* __restrict__ ffw1, const float* __restrict__ ffb1,
    const float* __restrict__ ffw2, const float* __restrict__ ffb2,
    const float* __restrict__ lng,  const float* __restrict__ lnb,
    const float* __restrict__ scw,  const float* __restrict__ scb,
    const float* __restrict__ mw1,  const float* __restrict__ mb1,
    const float* __restrict__ mw2,  const float* __restrict__ mb2,
    const float* __restrict__ outw, const float* __restrict__ outb,
    float* __restrict__ out)
{
    __shared__ SmemLayout s;
    const int tid  = threadIdx.x;
    const int lane = tid & 31;
    const int w    = tid >> 5;
    const int b    = blockIdx.x;

    // ---- tokens + embeddings (float4) ----
    if (tid < SEQ) s.toks[tid] = seqs[b * SEQ + tid];
    __syncthreads();
    {
        const float4* e4 = (const float4*)embed;
        float4* h4 = (float4*)s.h;
        #pragma unroll
        for (int r = 0; r < 4; r++) {
            int idx = tid + 128 * r;          // 0..511
            int t = idx >> 4, c = idx & 15;
            h4[idx] = e4[s.toks[t] * 16 + c];
        }
    }
    __syncthreads();

    float* scratch = s.M;  // 4 warps x 1024 floats (spans M+Vv)

    // ---- encode: warp w handles tokens {w, w+4, ..., w+28} ----
    {
        // layer 1: lane owns cols [4*lane, 4*lane+4)
        const float4* w1_4 = (const float4*)ffw1;
        float4 bb = ((const float4*)ffb1)[lane];
        float4 acc[8];
        #pragma unroll
        for (int tk = 0; tk < 8; tk++) acc[tk] = bb;
        #pragma unroll 4
        for (int i = 0; i < Hd; i++) {
            float4 wv = w1_4[i * 32 + lane];
            #pragma unroll
            for (int tk = 0; tk < 8; tk++) {
                float ev = s.h[(w + 4 * tk) * Hd + i];
                acc[tk].x = fmaf(ev, wv.x, acc[tk].x);
                acc[tk].y = fmaf(ev, wv.y, acc[tk].y);
                acc[tk].z = fmaf(ev, wv.z, acc[tk].z);
                acc[tk].w = fmaf(ev, wv.w, acc[tk].w);
            }
        }
        float4* sc4 = (float4*)scratch;
        #pragma unroll
        for (int tk = 0; tk < 8; tk++) {
            float4 r;
            r.x = fmaxf(acc[tk].x, 0.0f);
            r.y = fmaxf(acc[tk].y, 0.0f);
            r.z = fmaxf(acc[tk].z, 0.0f);
            r.w = fmaxf(acc[tk].w, 0.0f);
            sc4[w * 256 + tk * 32 + lane] = r;
        }
        __syncwarp();

        // layer 2: lane owns cols [2*lane, 2*lane+2)
        const float2* w2_2 = (const float2*)ffw2;
        float2 fb = ((const float2*)ffb2)[lane];
        float2 a2[8];
        #pragma unroll
        for (int tk = 0; tk < 8; tk++) a2[tk] = fb;
        #pragma unroll 4
        for (int i = 0; i < 2 * Hd; i++) {
            float2 wv = w2_2[i * 32 + lane];
            #pragma unroll
            for (int tk = 0; tk < 8; tk++) {
                float hv = scratch[w * 1024 + tk * 128 + i];
                a2[tk].x = fmaf(hv, wv.x, a2[tk].x);
                a2[tk].y = fmaf(hv, wv.y, a2[tk].y);
            }
        }

        // residual + layernorm
        float2 g2  = ((const float2*)lng)[lane];
        float2 be2 = ((const float2*)lnb)[lane];
        float2* h2 = (float2*)s.h;
        #pragma unroll
        for (int tk = 0; tk < 8; tk++) {
            int t = w + 4 * tk;
            float2 x = h2[t * 32 + lane];
            x.x += a2[tk].x; x.y += a2[tk].y;
            float mean = wredsum(x.x + x.y) * (1.0f / 64.0f);
            float d0 = x.x - mean, d1 = x.y - mean;
            float var = wredsum(d0 * d0 + d1 * d1) * (1.0f / 64.0f);
            float rs = rsqrtf(var + 1e-5f);
            float2 r;
            r.x = fmaf(d0 * rs, g2.x, be2.x);
            r.y = fmaf(d1 * rs, g2.y, be2.y);
            h2[t * 32 + lane] = r;
        }
    }
    __syncthreads();

    // ---- scores ----
    for (int p = w; p < NPAIR; p += 4) {
        const float* kk = &s.h[(2 * p)     * Hd];
        const float* vv = &s.h[(2 * p + 1) * Hd];
        float acc = kk[lane]      * scw[lane]
                  + kk[lane + 32] * scw[lane + 32]
                  + vv[lane]      * scw[lane + 64]
                  + vv[lane + 32] * scw[lane + 96];
        acc = wredsum(acc);
        if (lane == 0) s.scores[p] = acc + scb[0];
    }
    __syncthreads();

    // ---- evict-min (thread 0) overlapped with Adam state init (all) ----
    if (tid == 0) {
        #pragma unroll
        for (int i = 0; i < CAP; i++) { s.ord[i] = i; s.esc[i] = s.scores[i]; }
        for (int n = CAP; n < NPAIR; n++) {
            int mi = 0; float mv = s.esc[0];
            #pragma unroll
            for (int i = 1; i < CAP; i++) if (s.esc[i] < mv) { mv = s.esc[i]; mi = i; }
            for (int i = mi; i < CAP - 1; i++) { s.ord[i] = s.ord[i+1]; s.esc[i] = s.esc[i+1]; }
            s.ord[CAP-1] = n; s.esc[CAP-1] = s.scores[n];
        }
    }
    {
        float4* P4 = (float4*)s.P;
        for (int q = tid; q < 384; q += 128) P4[q]       = ((const float4*)mw1)[q];
        for (int q = tid; q < 384; q += 128) P4[390 + q] = ((const float4*)mw2)[q];
        if (tid < 6)  P4[384 + tid] = ((const float4*)mb1)[tid];
        if (tid >= 32 && tid < 48) P4[774 + (tid - 32)] = ((const float4*)mb2)[tid - 32];
        float4 z4 = make_float4(0.f, 0.f, 0.f, 0.f);
        float4* M4 = (float4*)s.M; float4* V4 = (float4*)s.Vv;
        for (int q = tid; q < 790; q += 128) { M4[q] = z4; V4[q] = z4; }
    }
    __syncthreads();

    // per-thread constant index seeds for the w1 update loop
    const int p0 = 2 * tid;
    const int j0 = p0 % 24;     // even
    const int i0 = p0 / 24;

    // ---- 8 inner Adam steps ----
    float pb1 = 1.0f, pb2 = 1.0f;
    #pragma unroll 1
    for (int st = 0; st < CAP; st++) {
        pb1 *= B1c; pb2 *= B2c;
        float inv1 = __fdividef(1.0f, 1.0f - pb1);
        float s2   = sqrtf(1.0f - pb2);
        float negC = -LRc * inv1 * s2;
        float epsT = EPSc * s2;
        int koff = (s.ord[st] << 1) * Hd;
        int voff = koff + Hd;

        // fwd layer1: 96 threads, 4 lanes per j
        if (tid < 96) {
            const int j  = ((tid >> 5) << 3) + ((tid & 31) >> 2);
            const int sl = tid & 3;
            float acc = 0.0f;
            #pragma unroll
            for (int k = 0; k < 16; k++)
                acc = fmaf(s.h[koff + sl + 4 * k], s.P[(sl + 4 * k) * INNER + j], acc);
            acc += __shfl_xor_sync(0xffffffffu, acc, 1);
            acc += __shfl_xor_sync(0xffffffffu, acc, 2);
            if (sl == 0) s.a1[j] = fmaxf(acc + s.P[OFF_B1 + j], 0.0f);
        }
        __syncthreads();

        // fwd layer2 + output grad: 128 threads, 2 lanes per o
        {
            const int o = tid >> 1, hf = tid & 1;
            const float* Wp = &s.P[OFF_W2 + (hf * 12) * Hd + o];
            const float* ap = &s.a1[hf * 12];
            float acc = 0.0f;
            #pragma unroll
            for (int k = 0; k < 12; k++) acc = fmaf(ap[k], Wp[k * Hd], acc);
            acc += __shfl_xor_sync(0xffffffffu, acc, 1);
            if (hf == 0)
                s.dout[o] = (acc + s.P[OFF_B2 + o] - s.h[voff + o]) * 0.03125f;
        }
        __syncthreads();

        // backward into hidden: 96 threads, rotated conflict-free
        if (tid < 96) {
            const int j  = ((tid >> 5) << 3) + ((tid & 31) >> 2);
            const int sl = tid & 3;
            float acc = 0.0f;
            #pragma unroll
            for (int k = 0; k < 16; k++) {
                int o = sl + 4 * ((j + k) & 15);
                acc = fmaf(s.P[OFF_W2 + j * Hd + o], s.dout[o], acc);
            }
            acc += __shfl_xor_sync(0xffffffffu, acc, 1);
            acc += __shfl_xor_sync(0xffffffffu, acc, 2);
            if (sl == 0) s.dz1[j] = (s.a1[j] > 0.0f) ? acc : 0.0f;
        }
        __syncthreads();

        // parameter updates (float2-vectorized, all 128 threads)
        {
            float2* P2 = (float2*)s.P;
            float2* M2 = (float2*)s.M;
            float2* V2 = (float2*)s.Vv;
            // w1: pairs (i*24+j, i*24+j+1), j even — incremental index
            int i = i0, j = j0;
            #pragma unroll
            for (int k = 0; k < 6; k++) {
                float hk = s.h[koff + i];
                float2 dz = *(const float2*)&s.dz1[j];
                adam2(P2, M2, V2, tid + 128 * k, hk * dz.x, hk * dz.y, negC, epsT);
                j += 16; i += 10; if (j >= 24) { j -= 24; i += 1; }
            }
            // w2: pairs (j*64+o, j*64+o+1), o even
            #pragma unroll
            for (int k = 0; k < 6; k++) {
                int p = p0 + 256 * k;
                int jj = p >> 6, o = p & 63;
                float av = s.a1[jj];
                float2 dv = *(const float2*)&s.dout[o];
                adam2(P2, M2, V2, 780 + tid + 128 * k, av * dv.x, av * dv.y, negC, epsT);
            }
            // b1 (tid 0..11), b2 (tid 32..63) in parallel warps
            if (tid < 12) {
                float2 dz = *(const float2*)&s.dz1[2 * tid];
                adam2(P2, M2, V2, 768 + tid, dz.x, dz.y, negC, epsT);
            }
            if (tid >= 32 && tid < 64) {
                int q = tid - 32;
                float2 dv = *(const float2*)&s.dout[2 * q];
                adam2(P2, M2, V2, 1548 + q, dv.x, dv.y, negC, epsT);
            }
        }
        __syncthreads();
    }

    // ---- query through finetuned MLP + output head ----
    {
        const int qoff = (SEQ - 2) * Hd;
        if (tid < 96) {
            const int j  = ((tid >> 5) << 3) + ((tid & 31) >> 2);
            const int sl = tid & 3;
            float acc = 0.0f;
            #pragma unroll
            for (int k = 0; k < 16; k++)
                acc = fmaf(s.h[qoff + sl + 4 * k], s.P[(sl + 4 * k) * INNER + j], acc);
            acc += __shfl_xor_sync(0xffffffffu, acc, 1);
            acc += __shfl_xor_sync(0xffffffffu, acc, 2);
            if (sl == 0) s.a1[j] = fmaxf(acc + s.P[OFF_B1 + j], 0.0f);
        }
        __syncthreads();
        {
            const int o = tid >> 1, hf = tid & 1;
            const float* Wp = &s.P[OFF_W2 + (hf * 12) * Hd + o];
            const float* ap = &s.a1[hf * 12];
            float acc = 0.0f;
            #pragma unroll
            for (int k = 0; k < 12; k++) acc = fmaf(ap[k], Wp[k * Hd], acc);
            acc += __shfl_xor_sync(0xffffffffu, acc, 1);
            if (hf == 0) s.dout[o] = acc + s.P[OFF_B2 + o];
        }
        __syncthreads();
        if (tid < Vd) {
            float acc = outb[tid];
            #pragma unroll 8
            for (int o = 0; o < Hd; o++)
                acc = fmaf(s.dout[o], outw[o * Vd + tid], acc);
            out[b * Vd + tid] = acc;
        }
    }
}

extern "C" void kernel_launch(void* const* d_in, const int* in_sizes, int n_in,
                              void* d_out, int out_size) {
    const int*   seqs  = (const int*)  d_in[0];
    const float* embed = (const float*)d_in[1];
    const float* ffw1  = (const float*)d_in[2];
    const float* ffb1  = (const float*)d_in[3];
    const float* ffw2  = (const float*)d_in[4];
    const float* ffb2  = (const float*)d_in[5];
    const float* lng   = (const float*)d_in[6];
    const float* lnb   = (const float*)d_in[7];
    const float* scw   = (const float*)d_in[8];
    const float* scb   = (const float*)d_in[9];
    const float* mw1   = (const float*)d_in[10];
    const float* mb1   = (const float*)d_in[11];
    const float* mw2   = (const float*)d_in[12];
    const float* mb2   = (const float*)d_in[13];
    const float* outw  = (const float*)d_in[14];
    const float* outb  = (const float*)d_in[15];
    float* out = (float*)d_out;

    int B = in_sizes[0] / SEQ;
    ttt_kernel<<<B, 128>>>(seqs, embed, ffw1, ffb1, ffw2, ffb2, lng, lnb,
                           scw, scb, mw1, mb1, mw2, mb2, outw, outb, out);
}

// round 7
// speedup vs baseline: 2.3289x; 1.0599x over previous
#include <cuda_runtime.h>

#define Hd 64
#define Vd 64
#define INNER 24
#define SEQ 32
#define CAP 8
#define NPAIR 15
#define LRc 0.05f
#define B1c 0.9f
#define B2c 0.999f
#define EPSc 1e-8f

#define NW1 (Hd*INNER)             // 1536
#define OFF_B1 NW1                 // 1536
#define OFF_W2 (NW1 + INNER)       // 1560
#define OFF_B2 (OFF_W2 + INNER*Hd) // 3096
#define NPARAM (OFF_B2 + Hd)       // 3160

struct __align__(16) SmemLayout {
    float h[SEQ*Hd];               // 2048 floats
    union {
        float scratch[4096];       // encode-only (4 warps x 1024)
        struct {
            float P[NPARAM];       // params  w1[i*24+j] | b1 | w2[j*64+o] | b2
            float a1[INNER];
            float dz1[INNER];
            float dout[Hd];
            float scores[NPAIR + 1];
            float esc[CAP];
            int   ord[CAP];
            int   toks[SEQ];       // only live before encode (pre-scratch)
        };
    };
};

__device__ __forceinline__ float wredsum(float x) {
    #pragma unroll
    for (int o = 16; o; o >>= 1) x += __shfl_xor_sync(0xffffffffu, x, o);
    return x;
}

// Exact eps-folded Adam, state (m,v) in REGISTERS, param pair in smem.
//   mhat/(sqrt(vhat)+eps) == m/(sqrt(v)+eps*s2) * (inv1*s2),  s2 = sqrt(1-b2^t)
__device__ __forceinline__ void adam2r(float2* __restrict__ P2, int f,
                                       float2& m, float2& v,
                                       float gx, float gy, float negC, float epsT) {
    m.x = fmaf(B1c, m.x, 0.1f * gx);
    m.y = fmaf(B1c, m.y, 0.1f * gy);
    v.x = fmaf(B2c, v.x, 0.001f * gx * gx);
    v.y = fmaf(B2c, v.y, 0.001f * gy * gy);
    float rx = __frsqrt_rn(v.x);
    float ry = __frsqrt_rn(v.y);
    float sx = (v.x > 0.0f) ? v.x * rx : 0.0f;   // sqrt(v), 0-safe
    float sy = (v.y > 0.0f) ? v.y * ry : 0.0f;
    float2 p = P2[f];
    p.x = fmaf(negC, __fdividef(m.x, sx + epsT), p.x);
    p.y = fmaf(negC, __fdividef(m.y, sy + epsT), p.y);
    P2[f] = p;
}

__global__ void __launch_bounds__(128, 4) ttt_kernel(
    const int*   __restrict__ seqs,
    const float* __restrict__ embed,
    const float* __restrict__ ffw1, const float* __restrict__ ffb1,
    const float* __restrict__ ffw2, const float* __restrict__ ffb2,
    const float* __restrict__ lng,  const float* __restrict__ lnb,
    const float* __restrict__ scw,  const float* __restrict__ scb,
    const float* __restrict__ mw1,  const float* __restrict__ mb1,
    const float* __restrict__ mw2,  const float* __restrict__ mb2,
    const float* __restrict__ outw, const float* __restrict__ outb,
    float* __restrict__ out)
{
    __shared__ SmemLayout s;
    const int tid  = threadIdx.x;
    const int lane = tid & 31;
    const int w    = tid >> 5;
    const int b    = blockIdx.x;

    // ---- tokens + embeddings (float4) ----
    if (tid < SEQ) s.toks[tid] = seqs[b * SEQ + tid];
    __syncthreads();
    {
        const float4* e4 = (const float4*)embed;
        float4* h4 = (float4*)s.h;
        #pragma unroll
        for (int r = 0; r < 4; r++) {
            int idx = tid + 128 * r;          // 0..511
            int t = idx >> 4, c = idx & 15;
            h4[idx] = e4[s.toks[t] * 16 + c];
        }
    }
    __syncthreads();

    // ---- encode: warp w handles tokens {w, w+4, ..., w+28} ----
    {
        // layer 1: lane owns cols [4*lane, 4*lane+4)
        const float4* w1_4 = (const float4*)ffw1;
        float4 bb = ((const float4*)ffb1)[lane];
        float4 acc[8];
        #pragma unroll
        for (int tk = 0; tk < 8; tk++) acc[tk] = bb;
        #pragma unroll 4
        for (int i = 0; i < Hd; i++) {
            float4 wv = w1_4[i * 32 + lane];
            #pragma unroll
            for (int tk = 0; tk < 8; tk++) {
                float ev = s.h[(w + 4 * tk) * Hd + i];
                acc[tk].x = fmaf(ev, wv.x, acc[tk].x);
                acc[tk].y = fmaf(ev, wv.y, acc[tk].y);
                acc[tk].z = fmaf(ev, wv.z, acc[tk].z);
                acc[tk].w = fmaf(ev, wv.w, acc[tk].w);
            }
        }
        float4* sc4 = (float4*)s.scratch;
        #pragma unroll
        for (int tk = 0; tk < 8; tk++) {
            float4 r;
            r.x = fmaxf(acc[tk].x, 0.0f);
            r.y = fmaxf(acc[tk].y, 0.0f);
            r.z = fmaxf(acc[tk].z, 0.0f);
            r.w = fmaxf(acc[tk].w, 0.0f);
            sc4[w * 256 + tk * 32 + lane] = r;
        }
        __syncwarp();

        // layer 2: lane owns cols [2*lane, 2*lane+2)
        const float2* w2_2 = (const float2*)ffw2;
        float2 fb = ((const float2*)ffb2)[lane];
        float2 a2[8];
        #pragma unroll
        for (int tk = 0; tk < 8; tk++) a2[tk] = fb;
        #pragma unroll 4
        for (int i = 0; i < 2 * Hd; i++) {
            float2 wv = w2_2[i * 32 + lane];
            #pragma unroll
            for (int tk = 0; tk < 8; tk++) {
                float hv = s.scratch[w * 1024 + tk * 128 + i];
                a2[tk].x = fmaf(hv, wv.x, a2[tk].x);
                a2[tk].y = fmaf(hv, wv.y, a2[tk].y);
            }
        }

        // residual + layernorm
        float2 g2  = ((const float2*)lng)[lane];
        float2 be2 = ((const float2*)lnb)[lane];
        float2* h2 = (float2*)s.h;
        #pragma unroll
        for (int tk = 0; tk < 8; tk++) {
            int t = w + 4 * tk;
            float2 x = h2[t * 32 + lane];
            x.x += a2[tk].x; x.y += a2[tk].y;
            float mean = wredsum(x.x + x.y) * (1.0f / 64.0f);
            float d0 = x.x - mean, d1 = x.y - mean;
            float var = wredsum(d0 * d0 + d1 * d1) * (1.0f / 64.0f);
            float rs = rsqrtf(var + 1e-5f);
            float2 r;
            r.x = fmaf(d0 * rs, g2.x, be2.x);
            r.y = fmaf(d1 * rs, g2.y, be2.y);
            h2[t * 32 + lane] = r;
        }
    }
    __syncthreads();

    // ---- scores (scratch dead from here; P/a1/... region live) ----
    for (int p = w; p < NPAIR; p += 4) {
        const float* kk = &s.h[(2 * p)     * Hd];
        const float* vv = &s.h[(2 * p + 1) * Hd];
        float acc = kk[lane]      * scw[lane]
                  + kk[lane + 32] * scw[lane + 32]
                  + vv[lane]      * scw[lane + 64]
                  + vv[lane + 32] * scw[lane + 96];
        acc = wredsum(acc);
        if (lane == 0) s.scores[p] = acc + scb[0];
    }
    __syncthreads();

    // ---- evict-min (thread 0) overlapped with P init (all) ----
    if (tid == 0) {
        #pragma unroll
        for (int i = 0; i < CAP; i++) { s.ord[i] = i; s.esc[i] = s.scores[i]; }
        for (int n = CAP; n < NPAIR; n++) {
            int mi = 0; float mv = s.esc[0];
            #pragma unroll
            for (int i = 1; i < CAP; i++) if (s.esc[i] < mv) { mv = s.esc[i]; mi = i; }
            for (int i = mi; i < CAP - 1; i++) { s.ord[i] = s.ord[i+1]; s.esc[i] = s.esc[i+1]; }
            s.ord[CAP-1] = n; s.esc[CAP-1] = s.scores[n];
        }
    }
    {
        float4* P4 = (float4*)s.P;
        for (int q = tid; q < 384; q += 128) P4[q]       = ((const float4*)mw1)[q];
        for (int q = tid; q < 384; q += 128) P4[390 + q] = ((const float4*)mw2)[q];
        if (tid < 6)  P4[384 + tid] = ((const float4*)mb1)[tid];
        if (tid >= 32 && tid < 48) P4[774 + (tid - 32)] = ((const float4*)mb2)[tid - 32];
    }
    __syncthreads();

    // per-thread constant index seeds for the w1 update loop
    const int p0 = 2 * tid;
    const int j0 = p0 % 24;     // even
    const int i0 = p0 / 24;

    // ---- Adam state in registers (same param indices every step) ----
    float2 mW1[6], vW1[6], mW2[6], vW2[6];
    float2 mB = make_float2(0.f, 0.f), vB = make_float2(0.f, 0.f);
    #pragma unroll
    for (int k = 0; k < 6; k++) {
        mW1[k] = make_float2(0.f, 0.f); vW1[k] = make_float2(0.f, 0.f);
        mW2[k] = make_float2(0.f, 0.f); vW2[k] = make_float2(0.f, 0.f);
    }

    // ---- 8 inner Adam steps ----
    float pb1 = 1.0f, pb2 = 1.0f;
    #pragma unroll 1
    for (int st = 0; st < CAP; st++) {
        pb1 *= B1c; pb2 *= B2c;
        float inv1 = __fdividef(1.0f, 1.0f - pb1);
        float s2   = sqrtf(1.0f - pb2);
        float negC = -LRc * inv1 * s2;
        float epsT = EPSc * s2;
        int koff = (s.ord[st] << 1) * Hd;
        int voff = koff + Hd;

        // fwd layer1: 96 threads, 4 lanes per j
        if (tid < 96) {
            const int j  = ((tid >> 5) << 3) + ((tid & 31) >> 2);
            const int sl = tid & 3;
            float acc = 0.0f;
            #pragma unroll
            for (int k = 0; k < 16; k++)
                acc = fmaf(s.h[koff + sl + 4 * k], s.P[(sl + 4 * k) * INNER + j], acc);
            acc += __shfl_xor_sync(0xffffffffu, acc, 1);
            acc += __shfl_xor_sync(0xffffffffu, acc, 2);
            if (sl == 0) s.a1[j] = fmaxf(acc + s.P[OFF_B1 + j], 0.0f);
        }
        __syncthreads();

        // fwd layer2 + output grad: 128 threads, 2 lanes per o
        {
            const int o = tid >> 1, hf = tid & 1;
            const float* Wp = &s.P[OFF_W2 + (hf * 12) * Hd + o];
            const float* ap = &s.a1[hf * 12];
            float acc = 0.0f;
            #pragma unroll
            for (int k = 0; k < 12; k++) acc = fmaf(ap[k], Wp[k * Hd], acc);
            acc += __shfl_xor_sync(0xffffffffu, acc, 1);
            if (hf == 0)
                s.dout[o] = (acc + s.P[OFF_B2 + o] - s.h[voff + o]) * 0.03125f;
        }
        __syncthreads();

        // backward into hidden: 96 threads, rotated conflict-free
        if (tid < 96) {
            const int j  = ((tid >> 5) << 3) + ((tid & 31) >> 2);
            const int sl = tid & 3;
            float acc = 0.0f;
            #pragma unroll
            for (int k = 0; k < 16; k++) {
                int o = sl + 4 * ((j + k) & 15);
                acc = fmaf(s.P[OFF_W2 + j * Hd + o], s.dout[o], acc);
            }
            acc += __shfl_xor_sync(0xffffffffu, acc, 1);
            acc += __shfl_xor_sync(0xffffffffu, acc, 2);
            if (sl == 0) s.dz1[j] = (s.a1[j] > 0.0f) ? acc : 0.0f;
        }
        __syncthreads();

        // parameter updates (float2, Adam state in registers)
        {
            float2* P2 = (float2*)s.P;
            // w1: pairs (i*24+j, i*24+j+1), j even — incremental index
            int i = i0, j = j0;
            #pragma unroll
            for (int k = 0; k < 6; k++) {
                float hk = s.h[koff + i];
                float2 dz = *(const float2*)&s.dz1[j];
                adam2r(P2, tid + 128 * k, mW1[k], vW1[k],
                       hk * dz.x, hk * dz.y, negC, epsT);
                j += 16; i += 10; if (j >= 24) { j -= 24; i += 1; }
            }
            // w2: pairs (j*64+o, j*64+o+1), o even
            #pragma unroll
            for (int k = 0; k < 6; k++) {
                int p = p0 + 256 * k;
                int jj = p >> 6, o = p & 63;
                float av = s.a1[jj];
                float2 dv = *(const float2*)&s.dout[o];
                adam2r(P2, 780 + tid + 128 * k, mW2[k], vW2[k],
                       av * dv.x, av * dv.y, negC, epsT);
            }
            // b1 (tid 0..11), b2 (tid 32..63) in parallel warps
            if (tid < 12) {
                float2 dz = *(const float2*)&s.dz1[2 * tid];
                adam2r(P2, 768 + tid, mB, vB, dz.x, dz.y, negC, epsT);
            }
            if (tid >= 32 && tid < 64) {
                int q = tid - 32;
                float2 dv = *(const float2*)&s.dout[2 * q];
                adam2r(P2, 1548 + q, mB, vB, dv.x, dv.y, negC, epsT);
            }
        }
        __syncthreads();
    }

    // ---- query through finetuned MLP + output head ----
    {
        const int qoff = (SEQ - 2) * Hd;
        if (tid < 96) {
            const int j  = ((tid >> 5) << 3) + ((tid & 31) >> 2);
            const int sl = tid & 3;
            float acc = 0.0f;
            #pragma unroll
            for (int k = 0; k < 16; k++)
                acc = fmaf(s.h[qoff + sl + 4 * k], s.P[(sl + 4 * k) * INNER + j], acc);
            acc += __shfl_xor_sync(0xffffffffu, acc, 1);
            acc += __shfl_xor_sync(0xffffffffu, acc, 2);
            if (sl == 0) s.a1[j] = fmaxf(acc + s.P[OFF_B1 + j], 0.0f);
        }
        __syncthreads();
        {
            const int o = tid >> 1, hf = tid & 1;
            const float* Wp = &s.P[OFF_W2 + (hf * 12) * Hd + o];
            const float* ap = &s.a1[hf * 12];
            float acc = 0.0f;
            #pragma unroll
            for (int k = 0; k < 12; k++) acc = fmaf(ap[k], Wp[k * Hd], acc);
            acc += __shfl_xor_sync(0xffffffffu, acc, 1);
            if (hf == 0) s.dout[o] = acc + s.P[OFF_B2 + o];
        }
        __syncthreads();
        if (tid < Vd) {
            float acc = outb[tid];
            #pragma unroll 8
            for (int o = 0; o < Hd; o++)
                acc = fmaf(s.dout[o], outw[o * Vd + tid], acc);
            out[b * Vd + tid] = acc;
        }
    }
}

extern "C" void kernel_launch(void* const* d_in, const int* in_sizes, int n_in,
                              void* d_out, int out_size) {
    const int*   seqs  = (const int*)  d_in[0];
    const float* embed = (const float*)d_in[1];
    const float* ffw1  = (const float*)d_in[2];
    const float* ffb1  = (const float*)d_in[3];
    const float* ffw2  = (const float*)d_in[4];
    const float* ffb2  = (const float*)d_in[5];
    const float* lng   = (const float*)d_in[6];
    const float* lnb   = (const float*)d_in[7];
    const float* scw   = (const float*)d_in[8];
    const float* scb   = (const float*)d_in[9];
    const float* mw1   = (const float*)d_in[10];
    const float* mb1   = (const float*)d_in[11];
    const float* mw2   = (const float*)d_in[12];
    const float* mb2   = (const float*)d_in[13];
    const float* outw  = (const float*)d_in[14];
    const float* outb  = (const float*)d_in[15];
    float* out = (float*)d_out;

    int B = in_sizes[0] / SEQ;
    ttt_kernel<<<B, 128>>>(seqs, embed, ffw1, ffb1, ffw2, ffb2, lng, lnb,
                           scw, scb, mw1, mb1, mw2, mb2, outw, outb, out);
}